// round 1
// baseline (speedup 1.0000x reference)
#include <cuda_runtime.h>
#include <math.h>
#include <float.h>

#define NMAX 16384
#define KNN 20

// ---------------- scratch (device globals; no allocation allowed) ----------
__device__ float g_Z [NMAX * 1216];  // [X1|X2|X3|H] concat, row stride 1216
__device__ float g_Y [NMAX * 64];    // per-block linear output
__device__ float g_P [NMAX * 96];    // maxpooled pairs
__device__ float g_Z1[NMAX * 256];
__device__ float g_Z2[NMAX * 256];
__device__ float g_Z3[NMAX * 128];
__device__ int   g_idx[NMAX * KNN];
__device__ float g_norm[NMAX];

// ---------------- row squared norms ----------------------------------------
__global__ void norms_kernel(const float* __restrict__ F, int ld, int D,
                             float* __restrict__ out, int n)
{
    int i = blockIdx.x * blockDim.x + threadIdx.x;
    if (i >= n) return;
    const float* r = F + (size_t)i * ld;
    float s = 0.f;
    for (int d = 0; d < D; d++) { float v = r[d]; s += v * v; }
    out[i] = s;
}

// ---------------- fused pairwise-distance + top-20 -------------------------
// One thread = one query. Block of 128 threads cycles candidate tiles of 128
// rows through shared memory; each thread keeps a private sorted top-20
// (key = ||c||^2 - 2 q.c, same ordering as d2; ties keep lower index,
// matching jax.lax.top_k).
template<int DP, int D>   // DP = D padded to multiple of 4
__global__ void knn_kernel(const float* __restrict__ F, int ld,
                           const float* __restrict__ norms,
                           int* __restrict__ out_idx, int n)
{
    const int TQ = 128, TC = 128;
    __shared__ __align__(16) float sC[TC * DP];
    __shared__ float sN[TC];
    const float4* sC4 = (const float4*)sC;

    int q = blockIdx.x * TQ + threadIdx.x;
    bool active = (q < n);

    float qf[DP];
    #pragma unroll
    for (int j = 0; j < DP; j++)
        qf[j] = (active && j < D) ? F[(size_t)q * ld + j] : 0.f;

    float best[KNN];
    int   bidx[KNN];
    #pragma unroll
    for (int k = 0; k < KNN; k++) { best[k] = 3.0e38f; bidx[k] = 0; }
    float worst = 3.0e38f;

    for (int tile = 0; tile < n; tile += TC) {
        __syncthreads();
        // cooperative load of candidate tile (zero-padded dims)
        for (int e = threadIdx.x; e < TC * DP; e += TQ) {
            int c = e / DP, d = e - c * DP;
            int row = tile + c;
            sC[e] = (row < n && d < D) ? F[(size_t)row * ld + d] : 0.f;
        }
        if (threadIdx.x < TC) {
            int row = tile + threadIdx.x;
            sN[threadIdx.x] = (row < n) ? norms[row] : 3.0e38f;
        }
        __syncthreads();

        if (active) {
            int cmax = min(TC, n - tile);
            for (int c = 0; c < cmax; c++) {
                float d0 = 0.f, d1 = 0.f, d2 = 0.f, d3 = 0.f;
                #pragma unroll
                for (int j = 0; j < DP; j += 4) {
                    float4 s = sC4[c * (DP / 4) + (j >> 2)];
                    d0 += qf[j + 0] * s.x;
                    d1 += qf[j + 1] * s.y;
                    d2 += qf[j + 2] * s.z;
                    d3 += qf[j + 3] * s.w;
                }
                float key = sN[c] - 2.0f * ((d0 + d1) + (d2 + d3));
                if (key < worst) {
                    int p = KNN - 1;
                    #pragma unroll 1
                    while (p > 0 && best[p - 1] > key) {
                        best[p] = best[p - 1];
                        bidx[p] = bidx[p - 1];
                        --p;
                    }
                    best[p] = key;
                    bidx[p] = tile + c;
                    worst = best[KNN - 1];
                }
            }
        }
    }

    if (active) {
        #pragma unroll
        for (int k = 0; k < KNN; k++) out_idx[(size_t)q * KNN + k] = bidx[k];
    }
}

// ---------------- generic fp32 tiled linear: C = A@W + b, optional ReLU ----
// A: [n, kin] row stride lda; W: [kin, kout] row-major; C: [n, kout] stride ldc
__global__ void linear_kernel(const float* __restrict__ A, int lda,
                              const float* __restrict__ W,
                              const float* __restrict__ bias,
                              float* __restrict__ C, int ldc,
                              int n, int kin, int kout, int relu)
{
    const int BM = 64, BN = 64, BK = 16;
    __shared__ __align__(16) float As[BK][BM];
    __shared__ __align__(16) float Bs[BK][BN];

    int bm = blockIdx.y * BM, bn = blockIdx.x * BN;
    int tid = threadIdx.x;
    int tx = tid & 15, ty = tid >> 4;

    float acc[4][4];
    #pragma unroll
    for (int i = 0; i < 4; i++)
        #pragma unroll
        for (int j = 0; j < 4; j++) acc[i][j] = 0.f;

    for (int k0 = 0; k0 < kin; k0 += BK) {
        #pragma unroll
        for (int i = 0; i < 4; i++) {
            int l = tid + i * 256;
            int k = l & 15, m = l >> 4;
            int gm = bm + m, gk = k0 + k;
            As[k][m] = (gm < n && gk < kin) ? A[(size_t)gm * lda + gk] : 0.f;
        }
        #pragma unroll
        for (int i = 0; i < 4; i++) {
            int l = tid + i * 256;
            int c = l & 63, k = l >> 6;
            int gk = k0 + k, gc = bn + c;
            Bs[k][c] = (gk < kin && gc < kout) ? W[(size_t)gk * kout + gc] : 0.f;
        }
        __syncthreads();
        #pragma unroll
        for (int k = 0; k < BK; k++) {
            float4 a4 = ((const float4*)As[k])[ty];
            float4 b4 = ((const float4*)Bs[k])[tx];
            float a[4] = {a4.x, a4.y, a4.z, a4.w};
            float b[4] = {b4.x, b4.y, b4.z, b4.w};
            #pragma unroll
            for (int i = 0; i < 4; i++)
                #pragma unroll
                for (int j = 0; j < 4; j++) acc[i][j] += a[i] * b[j];
        }
        __syncthreads();
    }

    #pragma unroll
    for (int i = 0; i < 4; i++) {
        int m = bm + ty * 4 + i;
        if (m >= n) continue;
        #pragma unroll
        for (int j = 0; j < 4; j++) {
            int c = bn + tx * 4 + j;
            if (c >= kout) continue;
            float v = acc[i][j] + bias[c];
            if (relu) v = fmaxf(v, 0.f);
            C[(size_t)m * ldc + c] = v;
        }
    }
}

// ---------------- gather + max over KNN neighbors --------------------------
// out[i, :] (64 wide, stride ldo) = max_k Y[idx[i,k], :]
__global__ void gathermax_kernel(const float* __restrict__ Y,
                                 const int* __restrict__ idx,
                                 float* __restrict__ out, int ldo, int n)
{
    int i = blockIdx.x;
    if (i >= n) return;
    int d = threadIdx.x; // 64 threads
    const int* ip = idx + (size_t)i * KNN;
    float m = -FLT_MAX;
    #pragma unroll
    for (int k = 0; k < KNN; k++) {
        int j = ip[k];
        m = fmaxf(m, Y[(size_t)j * 64 + d]);
    }
    out[(size_t)i * ldo + d] = m;
}

// ---------------- MaxPool1d(2) over first 192 cols of Z --------------------
__global__ void maxpool_kernel(const float* __restrict__ Z,
                               float* __restrict__ P, int n)
{
    int t = blockIdx.x * blockDim.x + threadIdx.x;
    if (t >= n * 96) return;
    int i = t / 96, j = t - i * 96;
    const float* r = Z + (size_t)i * 1216 + 2 * j;
    P[t] = fmaxf(r[0], r[1]);
}

// ---------------------------------------------------------------------------
extern "C" void kernel_launch(void* const* d_in, const int* in_sizes, int n_in,
                              void* d_out, int out_size)
{
    const float* X   = (const float*)d_in[0];
    const float* w1  = (const float*)d_in[1];
    const float* b1  = (const float*)d_in[2];
    const float* w2  = (const float*)d_in[3];
    const float* b2  = (const float*)d_in[4];
    const float* w3  = (const float*)d_in[5];
    const float* b3  = (const float*)d_in[6];
    const float* wc1 = (const float*)d_in[7];
    const float* bc1 = (const float*)d_in[8];
    const float* wc2 = (const float*)d_in[9];
    const float* bc2 = (const float*)d_in[10];
    const float* wc3 = (const float*)d_in[11];
    const float* bc3 = (const float*)d_in[12];
    const float* wc4 = (const float*)d_in[13];
    const float* bc4 = (const float*)d_in[14];
    float* out = (float*)d_out;

    int n = in_sizes[0] / 9;
    if (n > NMAX) n = NMAX;

    float *Z, *Y, *P, *Z1, *Z2, *Z3, *nrm;
    int* idx;
    cudaGetSymbolAddress((void**)&Z,   g_Z);
    cudaGetSymbolAddress((void**)&Y,   g_Y);
    cudaGetSymbolAddress((void**)&P,   g_P);
    cudaGetSymbolAddress((void**)&Z1,  g_Z1);
    cudaGetSymbolAddress((void**)&Z2,  g_Z2);
    cudaGetSymbolAddress((void**)&Z3,  g_Z3);
    cudaGetSymbolAddress((void**)&nrm, g_norm);
    cudaGetSymbolAddress((void**)&idx, g_idx);

    int nb256 = (n + 255) / 256;
    int knnB  = (n + 127) / 128;

    auto lin = [&](const float* A, int lda, const float* W, const float* bias,
                   float* C, int ldc, int kin, int kout, int relu) {
        dim3 grid((kout + 63) / 64, (n + 63) / 64);
        linear_kernel<<<grid, 256>>>(A, lda, W, bias, C, ldc, n, kin, kout, relu);
    };

    // ---- Block 1: knn(X, D=9), Y1 = X@w1+b1, X1 = max-gather -> Z[:,0:64]
    norms_kernel<<<nb256, 256>>>(X, 9, 9, nrm, n);
    knn_kernel<12, 9><<<knnB, 128>>>(X, 9, nrm, idx, n);
    lin(X, 9, w1, b1, Y, 64, 9, 64, 0);
    gathermax_kernel<<<n, 64>>>(Y, idx, Z + 0, 1216, n);

    // ---- Block 2: knn(X1, D=64), Y2 = X1@w2+b2 -> Z[:,64:128]
    norms_kernel<<<nb256, 256>>>(Z + 0, 1216, 64, nrm, n);
    knn_kernel<64, 64><<<knnB, 128>>>(Z + 0, 1216, nrm, idx, n);
    lin(Z + 0, 1216, w2, b2, Y, 64, 64, 64, 0);
    gathermax_kernel<<<n, 64>>>(Y, idx, Z + 64, 1216, n);

    // ---- Block 3: knn(X2, D=64), Y3 = X2@w2+b2 -> Z[:,128:192]
    norms_kernel<<<nb256, 256>>>(Z + 64, 1216, 64, nrm, n);
    knn_kernel<64, 64><<<knnB, 128>>>(Z + 64, 1216, nrm, idx, n);
    lin(Z + 64, 1216, w2, b2, Y, 64, 64, 64, 0);
    gathermax_kernel<<<n, 64>>>(Y, idx, Z + 128, 1216, n);

    // ---- Head: P = maxpool2(Z[:,0:192]); H = P@w3+b3 -> Z[:,192:1216]
    maxpool_kernel<<<(n * 96 + 255) / 256, 256>>>(Z, P, n);
    lin(P, 96, w3, b3, Z + 192, 1216, 96, 1024, 0);

    // ---- Classifier MLP
    lin(Z,  1216, wc1, bc1, Z1, 256, 1216, 256, 1);
    lin(Z1, 256,  wc2, bc2, Z2, 256, 256,  256, 1);
    lin(Z2, 256,  wc3, bc3, Z3, 128, 256,  128, 1);
    lin(Z3, 128,  wc4, bc4, out, 3, 128,   3,  0);
}

// round 2
// speedup vs baseline: 3.1323x; 3.1323x over previous
#include <cuda_runtime.h>
#include <math.h>
#include <float.h>

#define NMAX 16384
#define KNN 20

// ---------------- scratch (device globals; no allocation allowed) ----------
__device__ float g_Z [NMAX * 1216];  // [X1|X2|X3|H] concat, row stride 1216
__device__ float g_Y [NMAX * 64];    // per-block linear output
__device__ float g_Fc[NMAX * 64];    // compact feature copy for kNN
__device__ float g_P [NMAX * 96];    // maxpooled pairs
__device__ float g_Z1[NMAX * 256];
__device__ float g_Z2[NMAX * 256];
__device__ float g_Z3[NMAX * 128];
__device__ int   g_idx[NMAX * KNN];
__device__ float g_norm[NMAX];

// ---------------- packed f32x2 helpers --------------------------------------
__device__ __forceinline__ void ffma2(unsigned long long& acc,
                                      unsigned long long a,
                                      unsigned long long b) {
    asm("fma.rn.f32x2 %0, %1, %2, %0;" : "+l"(acc) : "l"(a), "l"(b));
}
__device__ __forceinline__ unsigned long long splat2(float x) {
    unsigned int u = __float_as_uint(x);
    unsigned long long r;
    asm("mov.b64 %0, {%1, %1};" : "=l"(r) : "r"(u));
    return r;
}
__device__ __forceinline__ void unpack2(unsigned long long v, float& lo, float& hi) {
    unsigned int a, b;
    asm("mov.b64 {%0, %1}, %2;" : "=r"(a), "=r"(b) : "l"(v));
    lo = __uint_as_float(a);
    hi = __uint_as_float(b);
}

// ---------------- row squared norms ------------------------------------------
__global__ void norms_kernel(const float* __restrict__ F, int ld, int D,
                             float* __restrict__ out, int n)
{
    int i = blockIdx.x * blockDim.x + threadIdx.x;
    if (i >= n) return;
    const float* r = F + (size_t)i * ld;
    float s = 0.f;
    for (int d = 0; d < D; d++) { float v = r[d]; s += v * v; }
    out[i] = s;
}

// ---------------- top-k bubble insert (registers, fully unrolled) -----------
__device__ __forceinline__ void topk_insert(float (&bk)[KNN], int (&bi)[KNN],
                                            float kv, int ci)
{
    float vk = kv; int vi = ci;
    #pragma unroll
    for (int p = 0; p < KNN; ++p) {
        bool sw = vk < bk[p];
        float tf = bk[p]; int ti = bi[p];
        if (sw) { bk[p] = vk; bi[p] = vi; vk = tf; vi = ti; }
    }
}

// ---------------- fused tiled-GEMM kNN top-20 --------------------------------
// F: compact [n, D]. 128 queries per block, 256 threads.
// Per 128-candidate tile: dot tile via FFMA2 register GEMM -> shared -> scan.
// key = ||c||^2 - 2 q.c  (same ordering as squared L2; ties -> lower index).
template<int D, int DP>   // DP = D padded (mult of 4)
__global__ __launch_bounds__(256, 1)
void knn2_kernel(const float* __restrict__ F,
                 const float* __restrict__ norms,
                 int* __restrict__ out_idx, int n)
{
    const int TQ = 128, TC = 128;
    const int SQP = 132, SCP = 130, SP = 130;
    extern __shared__ float smem[];
    float* sQ = smem;                 // [DP][SQP]  (transposed queries)
    float* sC = sQ + DP * SQP;        // [DP][SCP]  (transposed candidates)
    float* S  = sC + DP * SCP;        // [TQ][SP]   (dot tile / merge scratch)
    float* sN = S + TQ * SP;          // [TC]

    const int tid = threadIdx.x;
    const int tx = tid & 15, ty = tid >> 4;
    const int q0 = blockIdx.x * TQ;

    // zero padded rows once
    if (DP > D) {
        for (int e = tid; e < (DP - D) * TQ; e += 256) {
            int d = D + e / TQ, c = e % TQ;
            sQ[d * SQP + c] = 0.f;
            sC[d * SCP + c] = 0.f;
        }
    }
    // load query tile transposed (coalesced global reads)
    for (int e = tid; e < TQ * D; e += 256) {
        int q = e / D, d = e - q * D;
        sQ[d * SQP + q] = F[(size_t)(q0 + q) * D + d];
    }

    float best[KNN]; int bidx[KNN];
    #pragma unroll
    for (int k = 0; k < KNN; k++) { best[k] = 3.0e38f; bidx[k] = 0; }
    float worst = 3.0e38f;

    const int selq = tid & 127, selh = tid >> 7;

    for (int tile = 0; tile < n; tile += TC) {
        __syncthreads();  // previous selection done; safe to overwrite sC/S
        for (int e = tid; e < TC * D; e += 256) {
            int c = e / D, d = e - c * D;
            sC[d * SCP + c] = F[(size_t)(tile + c) * D + d];
        }
        if (tid < TC) sN[tid] = norms[tile + tid];
        __syncthreads();

        // ---- register GEMM: 8 query rows x 8 candidate cols per thread ----
        unsigned long long acc[8][4];
        #pragma unroll
        for (int i = 0; i < 8; i++)
            #pragma unroll
            for (int j = 0; j < 4; j++) acc[i][j] = 0ULL;

        const float* qbase = sQ + ty * 8;
        const float* cbase = sC + tx * 8;
        #pragma unroll 4
        for (int k = 0; k < DP; k++) {
            const float* qr = qbase + k * SQP;
            float4 qa = *(const float4*)(qr);
            float4 qb = *(const float4*)(qr + 4);
            const unsigned long long* cr =
                (const unsigned long long*)(cbase + k * SCP);
            unsigned long long b0 = cr[0], b1 = cr[1], b2 = cr[2], b3 = cr[3];
            unsigned long long a0 = splat2(qa.x), a1 = splat2(qa.y);
            unsigned long long a2 = splat2(qa.z), a3 = splat2(qa.w);
            unsigned long long a4 = splat2(qb.x), a5 = splat2(qb.y);
            unsigned long long a6 = splat2(qb.z), a7 = splat2(qb.w);
            ffma2(acc[0][0], a0, b0); ffma2(acc[0][1], a0, b1);
            ffma2(acc[0][2], a0, b2); ffma2(acc[0][3], a0, b3);
            ffma2(acc[1][0], a1, b0); ffma2(acc[1][1], a1, b1);
            ffma2(acc[1][2], a1, b2); ffma2(acc[1][3], a1, b3);
            ffma2(acc[2][0], a2, b0); ffma2(acc[2][1], a2, b1);
            ffma2(acc[2][2], a2, b2); ffma2(acc[2][3], a2, b3);
            ffma2(acc[3][0], a3, b0); ffma2(acc[3][1], a3, b1);
            ffma2(acc[3][2], a3, b2); ffma2(acc[3][3], a3, b3);
            ffma2(acc[4][0], a4, b0); ffma2(acc[4][1], a4, b1);
            ffma2(acc[4][2], a4, b2); ffma2(acc[4][3], a4, b3);
            ffma2(acc[5][0], a5, b0); ffma2(acc[5][1], a5, b1);
            ffma2(acc[5][2], a5, b2); ffma2(acc[5][3], a5, b3);
            ffma2(acc[6][0], a6, b0); ffma2(acc[6][1], a6, b1);
            ffma2(acc[6][2], a6, b2); ffma2(acc[6][3], a6, b3);
            ffma2(acc[7][0], a7, b0); ffma2(acc[7][1], a7, b1);
            ffma2(acc[7][2], a7, b2); ffma2(acc[7][3], a7, b3);
        }
        // write dot tile to shared
        #pragma unroll
        for (int i = 0; i < 8; i++) {
            unsigned long long* srow =
                (unsigned long long*)(S + (ty * 8 + i) * SP + tx * 8);
            #pragma unroll
            for (int j = 0; j < 4; j++) srow[j] = acc[i][j];
        }
        __syncthreads();

        // ---- selection: 2 threads per query, 64 candidates each ----
        {
            const float* srow = S + selq * SP + selh * 64;
            const float* snp  = sN + selh * 64;
            int cbaseg = tile + selh * 64;
            #pragma unroll 4
            for (int j = 0; j < 32; j++) {
                float2 dp = *(const float2*)(srow + 2 * j);
                float2 sn = *(const float2*)(snp + 2 * j);
                float k0 = __fmaf_rn(-2.f, dp.x, sn.x);
                float k1 = __fmaf_rn(-2.f, dp.y, sn.y);
                if (k0 < worst) {
                    topk_insert(best, bidx, k0, cbaseg + 2 * j);
                    worst = best[KNN - 1];
                }
                if (k1 < worst) {
                    topk_insert(best, bidx, k1, cbaseg + 2 * j + 1);
                    worst = best[KNN - 1];
                }
            }
        }
    }

    // ---- merge the two half-lists per query (exact (key,idx) order) ----
    __syncthreads();
    float* keyBuf = S;                       // [128][40]
    int*   idxBuf = (int*)(S + 128 * 40);    // [128][40]
    #pragma unroll
    for (int p = 0; p < KNN; p++) {
        keyBuf[selq * 40 + selh * 20 + p] = best[p];
        idxBuf[selq * 40 + selh * 20 + p] = bidx[p];
    }
    __syncthreads();
    if (selh == 0) {
        const float* ka = keyBuf + selq * 40;
        const float* kb = ka + 20;
        const int*   ia = idxBuf + selq * 40;
        const int*   ib = ia + 20;
        int i = 0, j = 0;
        int* outp = out_idx + (size_t)(q0 + selq) * KNN;
        #pragma unroll
        for (int o = 0; o < KNN; o++) {
            float fa = ka[i], fb = kb[j];
            int va = ia[i], vb = ib[j];
            bool takeA = (fa < fb) || (fa == fb && va < vb);
            outp[o] = takeA ? va : vb;
            if (takeA) i++; else j++;
        }
    }
}

// ---------------- fp32 tiled linear (FFMA2): C = A@W + b, optional ReLU ----
__global__ void linear_kernel(const float* __restrict__ A, int lda,
                              const float* __restrict__ W,
                              const float* __restrict__ bias,
                              float* __restrict__ C, int ldc,
                              int n, int kin, int kout, int relu)
{
    const int BM = 64, BN = 64, BK = 16;
    __shared__ __align__(16) float As[BK][BM];
    __shared__ __align__(16) float Bs[BK][BN];

    int bm = blockIdx.y * BM, bn = blockIdx.x * BN;
    int tid = threadIdx.x;
    int tx = tid & 15, ty = tid >> 4;

    unsigned long long acc[4][2];
    #pragma unroll
    for (int i = 0; i < 4; i++) { acc[i][0] = 0ULL; acc[i][1] = 0ULL; }

    for (int k0 = 0; k0 < kin; k0 += BK) {
        #pragma unroll
        for (int i = 0; i < 4; i++) {
            int l = tid + i * 256;
            int k = l & 15, m = l >> 4;
            int gm = bm + m, gk = k0 + k;
            As[k][m] = (gm < n && gk < kin) ? A[(size_t)gm * lda + gk] : 0.f;
        }
        #pragma unroll
        for (int i = 0; i < 4; i++) {
            int l = tid + i * 256;
            int c = l & 63, k = l >> 6;
            int gk = k0 + k, gc = bn + c;
            Bs[k][c] = (gk < kin && gc < kout) ? W[(size_t)gk * kout + gc] : 0.f;
        }
        __syncthreads();
        #pragma unroll
        for (int k = 0; k < BK; k++) {
            float4 a4 = ((const float4*)As[k])[ty];
            const unsigned long long* br = (const unsigned long long*)Bs[k];
            unsigned long long b0 = br[tx * 2], b1 = br[tx * 2 + 1];
            unsigned long long s0 = splat2(a4.x), s1 = splat2(a4.y);
            unsigned long long s2 = splat2(a4.z), s3 = splat2(a4.w);
            ffma2(acc[0][0], s0, b0); ffma2(acc[0][1], s0, b1);
            ffma2(acc[1][0], s1, b0); ffma2(acc[1][1], s1, b1);
            ffma2(acc[2][0], s2, b0); ffma2(acc[2][1], s2, b1);
            ffma2(acc[3][0], s3, b0); ffma2(acc[3][1], s3, b1);
        }
        __syncthreads();
    }

    #pragma unroll
    for (int i = 0; i < 4; i++) {
        int m = bm + ty * 4 + i;
        if (m >= n) continue;
        #pragma unroll
        for (int j = 0; j < 2; j++) {
            float lo, hi;
            unpack2(acc[i][j], lo, hi);
            int c0 = bn + tx * 4 + 2 * j;
            if (c0 < kout) {
                float v = lo + bias[c0];
                if (relu) v = fmaxf(v, 0.f);
                C[(size_t)m * ldc + c0] = v;
            }
            if (c0 + 1 < kout) {
                float v = hi + bias[c0 + 1];
                if (relu) v = fmaxf(v, 0.f);
                C[(size_t)m * ldc + c0 + 1] = v;
            }
        }
    }
}

// ---------------- gather + max over KNN neighbors ---------------------------
__global__ void gathermax_kernel(const float* __restrict__ Y,
                                 const int* __restrict__ idx,
                                 float* __restrict__ out, int ldo,
                                 float* __restrict__ out2, int n)
{
    int i = blockIdx.x;
    if (i >= n) return;
    int d = threadIdx.x; // 64 threads
    const int* ip = idx + (size_t)i * KNN;
    float m = -FLT_MAX;
    #pragma unroll
    for (int k = 0; k < KNN; k++) {
        int j = ip[k];
        m = fmaxf(m, Y[(size_t)j * 64 + d]);
    }
    out[(size_t)i * ldo + d] = m;
    if (out2) out2[(size_t)i * 64 + d] = m;
}

// ---------------- MaxPool1d(2) over first 192 cols of Z ---------------------
__global__ void maxpool_kernel(const float* __restrict__ Z,
                               float* __restrict__ P, int n)
{
    int t = blockIdx.x * blockDim.x + threadIdx.x;
    if (t >= n * 96) return;
    int i = t / 96, j = t - i * 96;
    const float* r = Z + (size_t)i * 1216 + 2 * j;
    P[t] = fmaxf(r[0], r[1]);
}

// -----------------------------------------------------------------------------
extern "C" void kernel_launch(void* const* d_in, const int* in_sizes, int n_in,
                              void* d_out, int out_size)
{
    const float* X   = (const float*)d_in[0];
    const float* w1  = (const float*)d_in[1];
    const float* b1  = (const float*)d_in[2];
    const float* w2  = (const float*)d_in[3];
    const float* b2  = (const float*)d_in[4];
    const float* w3  = (const float*)d_in[5];
    const float* b3  = (const float*)d_in[6];
    const float* wc1 = (const float*)d_in[7];
    const float* bc1 = (const float*)d_in[8];
    const float* wc2 = (const float*)d_in[9];
    const float* bc2 = (const float*)d_in[10];
    const float* wc3 = (const float*)d_in[11];
    const float* bc3 = (const float*)d_in[12];
    const float* wc4 = (const float*)d_in[13];
    const float* bc4 = (const float*)d_in[14];
    float* out = (float*)d_out;

    int n = in_sizes[0] / 9;
    if (n > NMAX) n = NMAX;

    float *Z, *Y, *Fc, *P, *Z1, *Z2, *Z3, *nrm;
    int* idx;
    cudaGetSymbolAddress((void**)&Z,   g_Z);
    cudaGetSymbolAddress((void**)&Y,   g_Y);
    cudaGetSymbolAddress((void**)&Fc,  g_Fc);
    cudaGetSymbolAddress((void**)&P,   g_P);
    cudaGetSymbolAddress((void**)&Z1,  g_Z1);
    cudaGetSymbolAddress((void**)&Z2,  g_Z2);
    cudaGetSymbolAddress((void**)&Z3,  g_Z3);
    cudaGetSymbolAddress((void**)&nrm, g_norm);
    cudaGetSymbolAddress((void**)&idx, g_idx);

    int nb256 = (n + 255) / 256;
    int knnB  = (n + 127) / 128;

    const int SM9  = (12 * 132 + 12 * 130 + 128 * 130 + 128) * 4;
    const int SM64 = (64 * 132 + 64 * 130 + 128 * 130 + 128) * 4;
    cudaFuncSetAttribute(knn2_kernel<9, 12>,
                         cudaFuncAttributeMaxDynamicSharedMemorySize, SM9);
    cudaFuncSetAttribute(knn2_kernel<64, 64>,
                         cudaFuncAttributeMaxDynamicSharedMemorySize, SM64);

    auto lin = [&](const float* A, int lda, const float* W, const float* bias,
                   float* C, int ldc, int kin, int kout, int relu) {
        dim3 grid((kout + 63) / 64, (n + 63) / 64);
        linear_kernel<<<grid, 256>>>(A, lda, W, bias, C, ldc, n, kin, kout, relu);
    };

    // ---- Block 1: knn(X, D=9), Y1 = X@w1+b1, X1 = max-gather
    norms_kernel<<<nb256, 256>>>(X, 9, 9, nrm, n);
    knn2_kernel<9, 12><<<knnB, 256, SM9>>>(X, nrm, idx, n);
    lin(X, 9, w1, b1, Y, 64, 9, 64, 0);
    gathermax_kernel<<<n, 64>>>(Y, idx, Z + 0, 1216, Fc, n);

    // ---- Block 2: knn(X1, D=64), Y2 = X1@w2+b2
    norms_kernel<<<nb256, 256>>>(Fc, 64, 64, nrm, n);
    knn2_kernel<64, 64><<<knnB, 256, SM64>>>(Fc, nrm, idx, n);
    lin(Fc, 64, w2, b2, Y, 64, 64, 64, 0);
    gathermax_kernel<<<n, 64>>>(Y, idx, Z + 64, 1216, Fc, n);

    // ---- Block 3: knn(X2, D=64), Y3 = X2@w2+b2
    norms_kernel<<<nb256, 256>>>(Fc, 64, 64, nrm, n);
    knn2_kernel<64, 64><<<knnB, 256, SM64>>>(Fc, nrm, idx, n);
    lin(Fc, 64, w2, b2, Y, 64, 64, 64, 0);
    gathermax_kernel<<<n, 64>>>(Y, idx, Z + 128, 1216, (float*)0, n);

    // ---- Head: P = maxpool2(Z[:,0:192]); H = P@w3+b3 -> Z[:,192:1216]
    maxpool_kernel<<<(n * 96 + 255) / 256, 256>>>(Z, P, n);
    lin(P, 96, w3, b3, Z + 192, 1216, 96, 1024, 0);

    // ---- Classifier MLP
    lin(Z,  1216, wc1, bc1, Z1, 256, 1216, 256, 1);
    lin(Z1, 256,  wc2, bc2, Z2, 256, 256,  256, 1);
    lin(Z2, 256,  wc3, bc3, Z3, 128, 256,  128, 1);
    lin(Z3, 128,  wc4, bc4, out, 3, 128,   3,  0);
}

// round 4
// speedup vs baseline: 4.0917x; 1.3063x over previous
#include <cuda_runtime.h>
#include <cuda_bf16.h>
#include <math.h>
#include <float.h>
#include <stdint.h>

#define NMAX 16384
#define KNN 20

// ---------------- scratch (device globals; no allocation allowed) ----------
__device__ float g_Z [NMAX * 1216];
__device__ float g_Y [NMAX * 64];
__device__ float g_Fc[NMAX * 64];
__device__ float g_P [NMAX * 96];
__device__ float g_Z1[NMAX * 256];
__device__ float g_Z2[NMAX * 256];
__device__ float g_Z3[NMAX * 128];
__device__ int   g_idx[NMAX * KNN];
__device__ float g_norm[NMAX];
__device__ __nv_bfloat16 g_hi[NMAX * 64];
__device__ __nv_bfloat16 g_lo[NMAX * 64];

// ---------------- helpers ----------------------------------------------------
__device__ __forceinline__ uint32_t smem_to_u32(const void* p) {
    uint32_t a;
    asm("{ .reg .u64 t; cvta.to.shared.u64 t, %1; cvt.u32.u64 %0, t; }"
        : "=r"(a) : "l"(p));
    return a;
}
__device__ __forceinline__ void cp_async16(uint32_t dst, const void* src) {
    asm volatile("cp.async.cg.shared.global [%0], [%1], 16;"
                 :: "r"(dst), "l"(src) : "memory");
}
__device__ __forceinline__ void cp_commit() {
    asm volatile("cp.async.commit_group;" ::: "memory");
}
__device__ __forceinline__ void cp_wait0() {
    asm volatile("cp.async.wait_group 0;" ::: "memory");
}
__device__ __forceinline__ void ldsm_x4(uint32_t& r0, uint32_t& r1,
                                        uint32_t& r2, uint32_t& r3, uint32_t a) {
    asm volatile("ldmatrix.sync.aligned.m8n8.x4.shared.b16 {%0,%1,%2,%3}, [%4];"
                 : "=r"(r0), "=r"(r1), "=r"(r2), "=r"(r3) : "r"(a));
}
__device__ __forceinline__ void mma_bf16(float& c0, float& c1, float& c2, float& c3,
                                         uint32_t a0, uint32_t a1, uint32_t a2, uint32_t a3,
                                         uint32_t b0, uint32_t b1) {
    asm volatile("mma.sync.aligned.m16n8k16.row.col.f32.bf16.bf16.f32 "
                 "{%0,%1,%2,%3}, {%4,%5,%6,%7}, {%8,%9}, {%0,%1,%2,%3};"
                 : "+f"(c0), "+f"(c1), "+f"(c2), "+f"(c3)
                 : "r"(a0), "r"(a1), "r"(a2), "r"(a3), "r"(b0), "r"(b1));
}

// ---------------- packed f32x2 helpers --------------------------------------
typedef unsigned long long ull;
__device__ __forceinline__ void ffma2(ull& acc, ull a, ull b) {
    asm("fma.rn.f32x2 %0, %1, %2, %0;" : "+l"(acc) : "l"(a), "l"(b));
}
__device__ __forceinline__ ull splat2(float x) {
    unsigned int u = __float_as_uint(x);
    ull r;
    asm("mov.b64 %0, {%1, %1};" : "=l"(r) : "r"(u));
    return r;
}
__device__ __forceinline__ void unpack2(ull v, float& lo, float& hi) {
    unsigned int a, b;
    asm("mov.b64 {%0, %1}, %2;" : "=r"(a), "=r"(b) : "l"(v));
    lo = __uint_as_float(a); hi = __uint_as_float(b);
}

// ---------------- row squared norms ------------------------------------------
__global__ void norms_kernel(const float* __restrict__ F, int ld, int D,
                             float* __restrict__ out, int n)
{
    int i = blockIdx.x * blockDim.x + threadIdx.x;
    if (i >= n) return;
    const float* r = F + (size_t)i * ld;
    float s = 0.f;
    for (int d = 0; d < D; d++) { float v = r[d]; s += v * v; }
    out[i] = s;
}

// ---------------- fp32 -> bf16 hi/lo split -----------------------------------
template<int DB>
__global__ void split_kernel(const float* __restrict__ F, int ld, int D,
                             __nv_bfloat16* __restrict__ hi,
                             __nv_bfloat16* __restrict__ lo, int n)
{
    int t = blockIdx.x * blockDim.x + threadIdx.x;
    if (t >= n * DB) return;
    int r = t / DB, d = t - r * DB;
    float x = (d < D) ? F[(size_t)r * ld + d] : 0.f;
    __nv_bfloat16 h = __float2bfloat16(x);
    float rem = x - __bfloat162float(h);
    hi[t] = h;
    lo[t] = __float2bfloat16(rem);
}

// ---------------- top-k bubble insert ----------------------------------------
__device__ __forceinline__ void topk_insert(float (&bk)[KNN], int (&bi)[KNN],
                                            float kv, int ci)
{
    float vk = kv; int vi = ci;
    #pragma unroll
    for (int p = 0; p < KNN; ++p) {
        bool sw = vk < bk[p];
        float tf = bk[p]; int ti = bi[p];
        if (sw) { bk[p] = vk; bi[p] = vi; vk = tf; vi = ti; }
    }
}

// ---------------- mma.sync kNN top-20 ----------------------------------------
// 128 queries/CTA, 128-candidate tiles. bf16 hi/lo 3-term split GEMM on HMMA,
// cp.async double-buffered candidate tiles, shared dot tile, 2-thread/query
// selection + exact (key, lower index) merge (matches jax.lax.top_k).
template<int DB>   // bf16 K per term: 16 (D=9) or 64
__global__ __launch_bounds__(256, 1)
void knn_mma_kernel(const __nv_bfloat16* __restrict__ Fhi,
                    const __nv_bfloat16* __restrict__ Flo,
                    const float* __restrict__ norms,
                    int* __restrict__ out_idx, int n)
{
    constexpr int NSTEP = DB / 16;
    constexpr int CHB = DB / 8;          // 16B chunks per row
    constexpr int SQH = DB + 8;          // smem row stride in halves
    constexpr int QB  = 128 * SQH * 2;   // one 128-row tile, bytes
    constexpr int OFF_QHI = 1024;        // sN[2][128] lives at 0
    constexpr int OFF_QLO = OFF_QHI + QB;
    constexpr int OFF_C   = OFF_QLO + QB;       // [buf][hi|lo] 4 x QB
    constexpr int OFF_S   = OFF_C + 4 * QB;     // [128][130] float

    extern __shared__ char smem[];
    const uint32_t sb = smem_to_u32(smem);
    float* sN = (float*)smem;            // [2][128]
    float* S  = (float*)(smem + OFF_S);

    const int tid = threadIdx.x;
    const int warp = tid >> 5, lane = tid & 31;
    const int q0 = blockIdx.x * 128;

    auto load_tile = [&](uint32_t dstoff, const __nv_bfloat16* src) {
        #pragma unroll
        for (int e = tid; e < 128 * CHB; e += 256) {
            int r = e / CHB, c = e - r * CHB;
            cp_async16(sb + dstoff + (uint32_t)(r * SQH + c * 8) * 2,
                       src + (size_t)r * DB + c * 8);
        }
    };

    // queries (persistent) + first candidate tile + norms
    load_tile(OFF_QHI, Fhi + (size_t)q0 * DB);
    load_tile(OFF_QLO, Flo + (size_t)q0 * DB);
    load_tile(OFF_C,      Fhi);
    load_tile(OFF_C + QB, Flo);
    if (tid < 32) cp_async16(sb + tid * 16, norms + tid * 4);
    cp_commit();
    cp_wait0();
    __syncthreads();

    // ldmatrix lane addressing
    const int m0 = warp * 16;
    const uint32_t aOff = (uint32_t)(((m0 + (lane & 15)) * SQH + (lane >> 4) * 8) * 2);
    const uint32_t aHi = sb + OFF_QHI + aOff;
    const uint32_t aLo = sb + OFF_QLO + aOff;
    const uint32_t bOff = (uint32_t)((((lane & 7) + ((lane >> 4) << 3)) * SQH
                                      + ((lane >> 3) & 1) * 8) * 2);

    float best[KNN]; int bidx[KNN];
    #pragma unroll
    for (int k = 0; k < KNN; k++) { best[k] = 3.0e38f; bidx[k] = 0; }
    float worst = 3.0e38f;

    const int selq = tid & 127, selh = tid >> 7;
    const int T = n >> 7;

    for (int t = 0; t < T; t++) {
        const int cur = t & 1, nb = (t + 1) & 1;
        if (t + 1 < T) {
            int row0 = (t + 1) << 7;
            load_tile(OFF_C + nb * 2 * QB,      Fhi + (size_t)row0 * DB);
            load_tile(OFF_C + nb * 2 * QB + QB, Flo + (size_t)row0 * DB);
            if (tid < 32) cp_async16(sb + nb * 512 + tid * 16, norms + row0 + tid * 4);
        }
        cp_commit();

        // ---- GEMM: 3-term bf16 split, warp computes m16 x n128 ----
        float acc[16][4];
        #pragma unroll
        for (int f = 0; f < 16; f++)
            #pragma unroll
            for (int j = 0; j < 4; j++) acc[f][j] = 0.f;

        const uint32_t cHi = sb + OFF_C + (uint32_t)(cur * 2 * QB) + bOff;
        const uint32_t cLo = cHi + QB;

        #pragma unroll
        for (int term = 0; term < 3; term++) {
            uint32_t aBase = (term == 2) ? aLo : aHi;
            uint32_t bBase = (term == 1) ? cLo : cHi;
            #pragma unroll
            for (int k = 0; k < NSTEP; k++) {
                uint32_t a0, a1, a2, a3;
                ldsm_x4(a0, a1, a2, a3, aBase + k * 32);
                #pragma unroll
                for (int f = 0; f < 8; f++) {
                    uint32_t b0, b1, b2, b3;
                    ldsm_x4(b0, b1, b2, b3,
                            bBase + k * 32 + (uint32_t)(f * 16 * SQH * 2));
                    mma_bf16(acc[2*f][0], acc[2*f][1], acc[2*f][2], acc[2*f][3],
                             a0, a1, a2, a3, b0, b1);
                    mma_bf16(acc[2*f+1][0], acc[2*f+1][1], acc[2*f+1][2], acc[2*f+1][3],
                             a0, a1, a2, a3, b2, b3);
                }
            }
        }

        // ---- dot tile -> shared ----
        {
            int r0 = m0 + (lane >> 2);
            int cc = (lane & 3) * 2;
            #pragma unroll
            for (int f = 0; f < 16; f++) {
                *(float2*)&S[r0 * 130 + f * 8 + cc] =
                    make_float2(acc[f][0], acc[f][1]);
                *(float2*)&S[(r0 + 8) * 130 + f * 8 + cc] =
                    make_float2(acc[f][2], acc[f][3]);
            }
        }
        __syncthreads();

        // ---- selection: 2 threads per query, 64 candidates each ----
        {
            const float* srow = S + selq * 130 + selh * 64;
            const float* snp  = sN + cur * 128 + selh * 64;
            int cbaseg = (t << 7) + selh * 64;
            #pragma unroll 4
            for (int j = 0; j < 32; j++) {
                float2 dp = *(const float2*)(srow + 2 * j);
                float2 sn = *(const float2*)(snp + 2 * j);
                float k0 = __fmaf_rn(-2.f, dp.x, sn.x);
                float k1 = __fmaf_rn(-2.f, dp.y, sn.y);
                if (k0 < worst) {
                    topk_insert(best, bidx, k0, cbaseg + 2 * j);
                    worst = best[KNN - 1];
                }
                if (k1 < worst) {
                    topk_insert(best, bidx, k1, cbaseg + 2 * j + 1);
                    worst = best[KNN - 1];
                }
            }
        }
        cp_wait0();
        __syncthreads();
    }

    // ---- merge the two half-lists per query (exact (key,idx) order) ----
    float* keyBuf = S;                        // [128][40]
    int*   idxBuf = (int*)(S + 128 * 40);     // [128][40]
    #pragma unroll
    for (int p = 0; p < KNN; p++) {
        keyBuf[selq * 40 + selh * 20 + p] = best[p];
        idxBuf[selq * 40 + selh * 20 + p] = bidx[p];
    }
    __syncthreads();
    if (selh == 0) {
        const float* ka = keyBuf + selq * 40;
        const float* kb = ka + 20;
        const int*   ia = idxBuf + selq * 40;
        const int*   ib = ia + 20;
        int i = 0, j = 0;
        int* outp = out_idx + (size_t)(q0 + selq) * KNN;
        #pragma unroll
        for (int o = 0; o < KNN; o++) {
            float fa = ka[i], fb = kb[j];
            int va = ia[i], vb = ib[j];
            bool takeA = (fa < fb) || (fa == fb && va < vb);
            outp[o] = takeA ? va : vb;
            if (takeA) i++; else j++;
        }
    }
}

// ---------------- fp32 tiled linear (FFMA2 + global prefetch) ---------------
__global__ __launch_bounds__(256)
void linear_kernel(const float* __restrict__ A, int lda,
                   const float* __restrict__ W,
                   const float* __restrict__ bias,
                   float* __restrict__ C, int ldc,
                   int n, int kin, int kout, int relu)
{
    const int BK = 16;
    __shared__ __align__(16) float As[2][BK][64];
    __shared__ __align__(16) float Bs[2][BK][64];

    int bm = blockIdx.y * 64, bn = blockIdx.x * 64;
    int tid = threadIdx.x;
    int tx = tid & 15, ty = tid >> 4;

    ull acc[4][2];
    #pragma unroll
    for (int i = 0; i < 4; i++) { acc[i][0] = 0ULL; acc[i][1] = 0ULL; }

    float ra[4], rb[4];
    #pragma unroll
    for (int i = 0; i < 4; i++) {
        int l = tid + i * 256;
        { int k = l & 15, m = l >> 4; int gm = bm + m;
          ra[i] = (gm < n && k < kin) ? A[(size_t)gm * lda + k] : 0.f; }
        { int c = l & 63, k = l >> 6; int gc = bn + c;
          rb[i] = (k < kin && gc < kout) ? W[(size_t)k * kout + gc] : 0.f; }
    }

    int nk = (kin + BK - 1) / BK;
    for (int kt = 0; kt < nk; kt++) {
        int cur = kt & 1;
        #pragma unroll
        for (int i = 0; i < 4; i++) {
            int l = tid + i * 256;
            { int k = l & 15, m = l >> 4; As[cur][k][m] = ra[i]; }
            { int c = l & 63, k = l >> 6; Bs[cur][k][c] = rb[i]; }
        }
        __syncthreads();
        if (kt + 1 < nk) {
            int k0 = (kt + 1) * BK;
            #pragma unroll
            for (int i = 0; i < 4; i++) {
                int l = tid + i * 256;
                { int k = l & 15, m = l >> 4; int gm = bm + m, gk = k0 + k;
                  ra[i] = (gm < n && gk < kin) ? A[(size_t)gm * lda + gk] : 0.f; }
                { int c = l & 63, k = l >> 6; int gk = k0 + k, gc = bn + c;
                  rb[i] = (gk < kin && gc < kout) ? W[(size_t)gk * kout + gc] : 0.f; }
            }
        }
        #pragma unroll
        for (int k = 0; k < BK; k++) {
            float4 a4 = ((const float4*)As[cur][k])[ty];
            const ull* br = (const ull*)Bs[cur][k];
            ull b0 = br[tx * 2], b1 = br[tx * 2 + 1];
            ull s0 = splat2(a4.x), s1 = splat2(a4.y);
            ull s2 = splat2(a4.z), s3 = splat2(a4.w);
            ffma2(acc[0][0], s0, b0); ffma2(acc[0][1], s0, b1);
            ffma2(acc[1][0], s1, b0); ffma2(acc[1][1], s1, b1);
            ffma2(acc[2][0], s2, b0); ffma2(acc[2][1], s2, b1);
            ffma2(acc[3][0], s3, b0); ffma2(acc[3][1], s3, b1);
        }
        __syncthreads();
    }

    #pragma unroll
    for (int i = 0; i < 4; i++) {
        int m = bm + ty * 4 + i;
        if (m >= n) continue;
        #pragma unroll
        for (int j = 0; j < 2; j++) {
            float lo, hi;
            unpack2(acc[i][j], lo, hi);
            int c0 = bn + tx * 4 + 2 * j;
            if (c0 < kout) {
                float v = lo + bias[c0];
                if (relu) v = fmaxf(v, 0.f);
                C[(size_t)m * ldc + c0] = v;
            }
            if (c0 + 1 < kout) {
                float v = hi + bias[c0 + 1];
                if (relu) v = fmaxf(v, 0.f);
                C[(size_t)m * ldc + c0 + 1] = v;
            }
        }
    }
}

// ---------------- gather + max over KNN neighbors ---------------------------
__global__ void gathermax_kernel(const float* __restrict__ Y,
                                 const int* __restrict__ idx,
                                 float* __restrict__ out, int ldo,
                                 float* __restrict__ out2, int n)
{
    int i = blockIdx.x;
    if (i >= n) return;
    int d = threadIdx.x; // 64 threads
    const int* ip = idx + (size_t)i * KNN;
    float m = -FLT_MAX;
    #pragma unroll
    for (int k = 0; k < KNN; k++) {
        int j = ip[k];
        m = fmaxf(m, Y[(size_t)j * 64 + d]);
    }
    out[(size_t)i * ldo + d] = m;
    if (out2) out2[(size_t)i * 64 + d] = m;
}

// ---------------- MaxPool1d(2) over first 192 cols of Z ---------------------
__global__ void maxpool_kernel(const float* __restrict__ Z,
                               float* __restrict__ P, int n)
{
    int t = blockIdx.x * blockDim.x + threadIdx.x;
    if (t >= n * 96) return;
    int i = t / 96, j = t - i * 96;
    const float* r = Z + (size_t)i * 1216 + 2 * j;
    P[t] = fmaxf(r[0], r[1]);
}

// -----------------------------------------------------------------------------
extern "C" void kernel_launch(void* const* d_in, const int* in_sizes, int n_in,
                              void* d_out, int out_size)
{
    const float* X   = (const float*)d_in[0];
    const float* w1  = (const float*)d_in[1];
    const float* b1  = (const float*)d_in[2];
    const float* w2  = (const float*)d_in[3];
    const float* b2  = (const float*)d_in[4];
    const float* w3  = (const float*)d_in[5];
    const float* b3  = (const float*)d_in[6];
    const float* wc1 = (const float*)d_in[7];
    const float* bc1 = (const float*)d_in[8];
    const float* wc2 = (const float*)d_in[9];
    const float* bc2 = (const float*)d_in[10];
    const float* wc3 = (const float*)d_in[11];
    const float* bc3 = (const float*)d_in[12];
    const float* wc4 = (const float*)d_in[13];
    const float* bc4 = (const float*)d_in[14];
    float* out = (float*)d_out;

    int n = in_sizes[0] / 9;
    if (n > NMAX) n = NMAX;

    float *Z, *Y, *Fc, *P, *Z1, *Z2, *Z3, *nrm;
    int* idx;
    __nv_bfloat16 *hi, *lo;
    cudaGetSymbolAddress((void**)&Z,   g_Z);
    cudaGetSymbolAddress((void**)&Y,   g_Y);
    cudaGetSymbolAddress((void**)&Fc,  g_Fc);
    cudaGetSymbolAddress((void**)&P,   g_P);
    cudaGetSymbolAddress((void**)&Z1,  g_Z1);
    cudaGetSymbolAddress((void**)&Z2,  g_Z2);
    cudaGetSymbolAddress((void**)&Z3,  g_Z3);
    cudaGetSymbolAddress((void**)&nrm, g_norm);
    cudaGetSymbolAddress((void**)&idx, g_idx);
    cudaGetSymbolAddress((void**)&hi,  g_hi);
    cudaGetSymbolAddress((void**)&lo,  g_lo);

    int nb256 = (n + 255) / 256;
    int knnB  = n / 128;

    // smem sizes: 1024 + 6*QB + 128*130*4, QB = 128*(DB+8)*2
    const int SM16 = 1024 + 6 * (128 * 24 * 2) + 128 * 130 * 4;  // 104448
    const int SM64 = 1024 + 6 * (128 * 72 * 2) + 128 * 130 * 4;  // 178176
    cudaFuncSetAttribute(knn_mma_kernel<16>,
                         cudaFuncAttributeMaxDynamicSharedMemorySize, SM16);
    cudaFuncSetAttribute(knn_mma_kernel<64>,
                         cudaFuncAttributeMaxDynamicSharedMemorySize, SM64);

    auto lin = [&](const float* A, int lda, const float* W, const float* bias,
                   float* C, int ldc, int kin, int kout, int relu) {
        dim3 grid((kout + 63) / 64, (n + 63) / 64);
        linear_kernel<<<grid, 256>>>(A, lda, W, bias, C, ldc, n, kin, kout, relu);
    };

    // ---- Block 1: knn(X, D=9) on HMMA; Y1 = X@w1+b1; X1 = max-gather
    norms_kernel<<<nb256, 256>>>(X, 9, 9, nrm, n);
    split_kernel<16><<<(n * 16 + 255) / 256, 256>>>(X, 9, 9, hi, lo, n);
    knn_mma_kernel<16><<<knnB, 256, SM16>>>(hi, lo, nrm, idx, n);
    lin(X, 9, w1, b1, Y, 64, 9, 64, 0);
    gathermax_kernel<<<n, 64>>>(Y, idx, Z + 0, 1216, Fc, n);

    // ---- Block 2: knn(X1, D=64); Y2 = X1@w2+b2
    norms_kernel<<<nb256, 256>>>(Fc, 64, 64, nrm, n);
    split_kernel<64><<<(n * 64 + 255) / 256, 256>>>(Fc, 64, 64, hi, lo, n);
    knn_mma_kernel<64><<<knnB, 256, SM64>>>(hi, lo, nrm, idx, n);
    lin(Fc, 64, w2, b2, Y, 64, 64, 64, 0);
    gathermax_kernel<<<n, 64>>>(Y, idx, Z + 64, 1216, Fc, n);

    // ---- Block 3: knn(X2, D=64); Y3 = X2@w2+b2
    norms_kernel<<<nb256, 256>>>(Fc, 64, 64, nrm, n);
    split_kernel<64><<<(n * 64 + 255) / 256, 256>>>(Fc, 64, 64, hi, lo, n);
    knn_mma_kernel<64><<<knnB, 256, SM64>>>(hi, lo, nrm, idx, n);
    lin(Fc, 64, w2, b2, Y, 64, 64, 64, 0);
    gathermax_kernel<<<n, 64>>>(Y, idx, Z + 128, 1216, (float*)0, n);

    // ---- Head: P = maxpool2(Z[:,0:192]); H = P@w3+b3 -> Z[:,192:1216]
    maxpool_kernel<<<(n * 96 + 255) / 256, 256>>>(Z, P, n);
    lin(P, 96, w3, b3, Z + 192, 1216, 96, 1024, 0);

    // ---- Classifier MLP
    lin(Z,  1216, wc1, bc1, Z1, 256, 1216, 256, 1);
    lin(Z1, 256,  wc2, bc2, Z2, 256, 256,  256, 1);
    lin(Z2, 256,  wc3, bc3, Z3, 128, 256,  128, 1);
    lin(Z3, 128,  wc4, bc4, out, 3, 128,   3,  0);
}